// round 9
// baseline (speedup 1.0000x reference)
#include <cuda_runtime.h>

// MemoryModule: B=8,L=12,T=36,D=1024,F=3,C=32
//   mq[c,t] = sum_{f,g} Wm[c,f] Wq[c,g] G[t,f,g] + bm[c]*(Wq[c]·XLsum)
//           + bq[c]*(Wm[c]·XHsum[t]) + D*bm[c]*bq[c]
//   o[c,d]  = sum_f Wc[c,f] * (sum_t att[c,t]*xh[t,d,f]) + bc[c]
// v9: k_gram per-warp autonomous cp.async pipeline (no CTA barriers — breaks
//     the SM-wide load/compute lockstep that capped DRAM at 40%); k_score
//     fused into k_out (att computed under the tile-load shadow).

#define Bb 8
#define Ll 12
#define Tt 36
#define Dd 1024
#define Ff 3
#define Cc 32
#define BL (Bb * Ll)
#define DF (Dd * Ff)        // 3072
#define DC 128
#define CHUNKS (Dd / DC)    // 8

__device__ __align__(16) float g_G[4 * BL * Tt * 12];  // 4 d-slices of G[9]+XHsum[3]
__device__ __align__(16) float g_XL[4][BL][4];          // per-slice xl sums

#define FFMA2(d, a, b) \
    asm("fma.rn.f32x2 %0, %1, %2, %0;" : "+l"(d) : "l"(a), "l"(b))

#define PACKDUP(d, s) \
    asm("mov.b64 %0, {%1, %1};" : "=l"(d) : "f"(s))

#define CP16(dst, src) \
    asm volatile("cp.async.cg.shared.global [%0], [%1], 16;" :: "r"(dst), "l"(src))

union U2F { unsigned long long u; float2 f; };

// ---------------------------------------------------------------------------
// k_gram: CTA = (tg 0..8, dh 0..1, bl), 128 threads, NO CTA barriers.
// Warp w: dseg = w&1, t-pair = tg*4 + (w>>1)*2 + {0,1}. Each warp loads its
// own xl seg + 2 xh segs (own cp.async groups), computes task A while task
// B's loads are in flight. smem 36KB -> 6 CTAs/SM. Grid (18,96) x 128.
// ---------------------------------------------------------------------------
#define SEG_F 768                           // floats per 256-d segment
#define WARP_SMEM (3 * SEG_F)               // xl + bufA + bufB

template <bool AXL>
__device__ __forceinline__ void gram_task(
    const float* __restrict__ xp, const float* __restrict__ lp,
    int lane, int bl, int t, int slot)
{
    float V[12];
    #pragma unroll
    for (int j = 0; j < 12; j++) V[j] = 0.0f;
    float X0 = 0.0f, X1 = 0.0f, X2 = 0.0f;

    #pragma unroll
    for (int it = 0; it < 8; it++) {
        int o = it * 96 + lane * 3;
        float a0 = xp[o + 0], a1 = xp[o + 1], a2 = xp[o + 2];
        float b0 = lp[o + 0], b1 = lp[o + 1], b2 = lp[o + 2];
        V[0] = fmaf(a0, b0, V[0]); V[1] = fmaf(a0, b1, V[1]); V[2] = fmaf(a0, b2, V[2]);
        V[3] = fmaf(a1, b0, V[3]); V[4] = fmaf(a1, b1, V[4]); V[5] = fmaf(a1, b2, V[5]);
        V[6] = fmaf(a2, b0, V[6]); V[7] = fmaf(a2, b1, V[7]); V[8] = fmaf(a2, b2, V[8]);
        V[9] += a0; V[10] += a1; V[11] += a2;
        if (AXL) { X0 += b0; X1 += b1; X2 += b2; }
    }

    #pragma unroll
    for (int j = 0; j < 12; j++) {
        #pragma unroll
        for (int o = 16; o; o >>= 1) V[j] += __shfl_down_sync(~0u, V[j], o);
    }
    if (AXL) {
        #pragma unroll
        for (int o = 16; o; o >>= 1) {
            X0 += __shfl_down_sync(~0u, X0, o);
            X1 += __shfl_down_sync(~0u, X1, o);
            X2 += __shfl_down_sync(~0u, X2, o);
        }
    }
    if (lane == 0) {
        float* gp = g_G + (((size_t)slot * BL + bl) * Tt + t) * 12;
        *(float4*)(gp + 0) = make_float4(V[0], V[1], V[2], V[3]);
        *(float4*)(gp + 4) = make_float4(V[4], V[5], V[6], V[7]);
        *(float4*)(gp + 8) = make_float4(V[8], V[9], V[10], V[11]);
        if (AXL) {
            g_XL[slot][bl][0] = X0;
            g_XL[slot][bl][1] = X1;
            g_XL[slot][bl][2] = X2;
        }
    }
}

__global__ __launch_bounds__(128) void k_gram(
    const float* __restrict__ xh_g, const float* __restrict__ xl_g)
{
    extern __shared__ float sg[];           // [4 warps][2304]

    int bx = blockIdx.x, bl = blockIdx.y;
    int tg = bx % 9, dh = bx / 9;
    int tid = threadIdx.x, w = tid >> 5, lane = tid & 31;

    int seg = w & 1;
    int t0 = tg * 4 + (w >> 1) * 2;         // tasks t0, t0+1
    int slot = dh * 2 + seg;

    float* ws   = sg + w * WARP_SMEM;
    float* s_xl = ws;
    float* bA   = ws + SEG_F;
    float* bB   = ws + 2 * SEG_F;

    size_t dof = (size_t)dh * 1536 + seg * SEG_F;
    const float* xls = xl_g + (size_t)bl * DF + dof;
    const float* xh0 = xh_g + ((size_t)bl * Tt + t0) * DF + dof;
    const float* xh1 = xh0 + DF;            // t0+1

    // group 0: xl + task A;  group 1: task B   (all per-thread)
    #pragma unroll
    for (int k = 0; k < 6; k++) {
        int o = (lane + 32 * k) * 4;
        CP16((unsigned)__cvta_generic_to_shared(s_xl + o), xls + o);
        CP16((unsigned)__cvta_generic_to_shared(bA + o), xh0 + o);
    }
    asm volatile("cp.async.commit_group;");
    #pragma unroll
    for (int k = 0; k < 6; k++) {
        int o = (lane + 32 * k) * 4;
        CP16((unsigned)__cvta_generic_to_shared(bB + o), xh1 + o);
    }
    asm volatile("cp.async.commit_group;");

    asm volatile("cp.async.wait_group 1;");
    __syncwarp();
    if (tg == 0 && w < 2)
        gram_task<true>(bA, s_xl, lane, bl, t0, slot);
    else
        gram_task<false>(bA, s_xl, lane, bl, t0, slot);

    asm volatile("cp.async.wait_group 0;");
    __syncwarp();
    gram_task<false>(bB, s_xl, lane, bl, t0 + 1, slot);
}

// ---------------------------------------------------------------------------
// k_out (score fused): CTA = (bl, 128-d chunk). While the 54KB tile streams
// in via cp.async, the CTA computes att from g_G/g_XL into s_att. Then the
// proven register-blocked FFMA2 main loop. Grid 768 x 256, smem ~68KB,
// 3 CTAs/SM.
// ---------------------------------------------------------------------------
#define SM_TILE_F (Tt * DC * Ff)   // 13824
#define SM_ATT_F  (Tt * Cc)        // 1152
#define SM_XL_F   (DC * Ff)        // 384
#define SM_G_F    (Tt * 12)        // 432
#define SM_MQ_F   (Cc * Tt)        // 1152
#define KOUT_SMEM_F (SM_TILE_F + SM_ATT_F + SM_XL_F + SM_G_F + SM_MQ_F + 4)
#define T_SPLIT   12

__global__ __launch_bounds__(256, 3) void k_out(
    const float* __restrict__ xl_g, const float* __restrict__ xh_g,
    const float* __restrict__ Wq, const float* __restrict__ bq,
    const float* __restrict__ Wm, const float* __restrict__ bm,
    const float* __restrict__ Wc, const float* __restrict__ bc,
    float* __restrict__ out)
{
    extern __shared__ float sm[];
    float* s_tile = sm;
    float* s_att  = sm + SM_TILE_F;
    float* s_xl   = sm + SM_TILE_F + SM_ATT_F;
    float* s_G    = sm + SM_TILE_F + SM_ATT_F + SM_XL_F;
    float* s_mq   = sm + SM_TILE_F + SM_ATT_F + SM_XL_F + SM_G_F;   // [Cc][Tt]
    float* s_XL   = sm + SM_TILE_F + SM_ATT_F + SM_XL_F + SM_G_F + SM_MQ_F;

    int blk = blockIdx.x;
    int bl = blk / CHUNKS, chunk = blk - bl * CHUNKS;
    int b = bl / Ll, l = bl - b * Ll;
    int tid = threadIdx.x;
    int wid = tid >> 5, lane = tid & 31;

    const float* xh_bl  = xh_g + (size_t)bl * Tt * DF + chunk * DC * Ff;
    const float* xl_src = xl_g + (size_t)bl * DF + chunk * DC * Ff;

    // ---- issue tile + xl copies (groups A, B) ----
    {
        int j = tid - 160;                  // threads 160..255 -> xl cp16 0..95
        if (j >= 0)
            CP16((unsigned)__cvta_generic_to_shared(s_xl + j * 4), xl_src + j * 4);
    }
    #pragma unroll
    for (int rr = 0; rr < 2; rr++) {
        int r = wid + rr * 8;
        if (r < T_SPLIT) {
            const float* sb = xh_bl + (size_t)r * DF;
            float* db = s_tile + r * (DC * Ff);
            #pragma unroll
            for (int s = 0; s < 3; s++) {
                int off = s * 128 + lane * 4;
                CP16((unsigned)__cvta_generic_to_shared(db + off), sb + off);
            }
        }
    }
    asm volatile("cp.async.commit_group;");
    #pragma unroll
    for (int rr = 0; rr < 3; rr++) {
        int r = T_SPLIT + wid + rr * 8;
        const float* sb = xh_bl + (size_t)r * DF;
        float* db = s_tile + r * (DC * Ff);
        #pragma unroll
        for (int s = 0; s < 3; s++) {
            int off = s * 128 + lane * 4;
            CP16((unsigned)__cvta_generic_to_shared(db + off), sb + off);
        }
    }
    asm volatile("cp.async.commit_group;");

    // ---- att computation (hidden under tile load) ----
    for (int i = tid; i < SM_G_F; i += 256)
        s_G[i] = g_G[((size_t)0 * BL + bl) * SM_G_F + i]
               + g_G[((size_t)1 * BL + bl) * SM_G_F + i]
               + g_G[((size_t)2 * BL + bl) * SM_G_F + i]
               + g_G[((size_t)3 * BL + bl) * SM_G_F + i];
    if (tid < 3)
        s_XL[tid] = g_XL[0][bl][tid] + g_XL[1][bl][tid]
                  + g_XL[2][bl][tid] + g_XL[3][bl][tid];
    __syncthreads();

    for (int i = tid; i < Cc * Tt; i += 256) {
        int c = i / Tt, t = i - c * Tt;
        float wm0 = Wm[c * 3 + 0], wm1 = Wm[c * 3 + 1], wm2 = Wm[c * 3 + 2];
        float wq0 = Wq[c * 3 + 0], wq1 = Wq[c * 3 + 1], wq2 = Wq[c * 3 + 2];
        float bmc = bm[c], bqc = bq[c];
        const float* Gp = s_G + t * 12;
        float v = wm0 * (wq0 * Gp[0] + wq1 * Gp[1] + wq2 * Gp[2])
                + wm1 * (wq0 * Gp[3] + wq1 * Gp[4] + wq2 * Gp[5])
                + wm2 * (wq0 * Gp[6] + wq1 * Gp[7] + wq2 * Gp[8])
                + bmc * (wq0 * s_XL[0] + wq1 * s_XL[1] + wq2 * s_XL[2])
                + bqc * (wm0 * Gp[9] + wm1 * Gp[10] + wm2 * Gp[11])
                + (float)Dd * bmc * bqc;
        s_mq[c * Tt + t] = fmaxf(v, 0.0f);
    }
    __syncthreads();

    #pragma unroll
    for (int k = 0; k < 4; k++) {
        int c = wid + 8 * k;
        float v0 = s_mq[c * Tt + lane];
        float v1 = (lane < Tt - 32) ? s_mq[c * Tt + lane + 32] : -3.0e38f;
        float mx = fmaxf(v0, v1);
        #pragma unroll
        for (int o = 16; o; o >>= 1) mx = fmaxf(mx, __shfl_xor_sync(~0u, mx, o));
        float e0 = __expf(v0 - mx);
        float e1 = (lane < Tt - 32) ? __expf(v1 - mx) : 0.0f;
        float s = e0 + e1;
        #pragma unroll
        for (int o = 16; o; o >>= 1) s += __shfl_xor_sync(~0u, s, o);
        float inv = 1.0f / s;
        s_att[lane * Cc + c] = e0 * inv;
        if (lane < Tt - 32) s_att[(lane + 32) * Cc + c] = e1 * inv;
    }
    __syncthreads();

    // ---- main accumulation ----
    int cg = lane >> 3, dp = lane & 7;
    int dloc = wid * 16 + dp * 2;

    unsigned long long A[24];
    #pragma unroll
    for (int k = 0; k < 24; k++) A[k] = 0ull;

    const float* ab = s_att + cg * 8;                    // + t*32
    const unsigned long long* tb =
        (const unsigned long long*)(s_tile + dloc * Ff); // + t*192 (u64 units)

    asm volatile("cp.async.wait_group 1;");
    __syncthreads();

    #pragma unroll 2
    for (int t = 0; t < T_SPLIT; t++) {
        float4 a0 = *(const float4*)(ab + t * Cc);
        float4 a1 = *(const float4*)(ab + t * Cc + 4);
        unsigned long long x0 = tb[t * 192 + 0];
        unsigned long long x1 = tb[t * 192 + 1];
        unsigned long long x2 = tb[t * 192 + 2];
        unsigned long long p0, p1, p2, p3, p4, p5, p6, p7;
        PACKDUP(p0, a0.x); PACKDUP(p1, a0.y); PACKDUP(p2, a0.z); PACKDUP(p3, a0.w);
        PACKDUP(p4, a1.x); PACKDUP(p5, a1.y); PACKDUP(p6, a1.z); PACKDUP(p7, a1.w);
        unsigned long long av[8] = {p0, p1, p2, p3, p4, p5, p6, p7};
        #pragma unroll
        for (int k = 0; k < 8; k++) {
            FFMA2(A[3 * k + 0], x0, av[k]);
            FFMA2(A[3 * k + 1], x1, av[k]);
            FFMA2(A[3 * k + 2], x2, av[k]);
        }
    }

    asm volatile("cp.async.wait_group 0;");
    __syncthreads();

    #pragma unroll 2
    for (int t = T_SPLIT; t < Tt; t++) {
        float4 a0 = *(const float4*)(ab + t * Cc);
        float4 a1 = *(const float4*)(ab + t * Cc + 4);
        unsigned long long x0 = tb[t * 192 + 0];
        unsigned long long x1 = tb[t * 192 + 1];
        unsigned long long x2 = tb[t * 192 + 2];
        unsigned long long p0, p1, p2, p3, p4, p5, p6, p7;
        PACKDUP(p0, a0.x); PACKDUP(p1, a0.y); PACKDUP(p2, a0.z); PACKDUP(p3, a0.w);
        PACKDUP(p4, a1.x); PACKDUP(p5, a1.y); PACKDUP(p6, a1.z); PACKDUP(p7, a1.w);
        unsigned long long av[8] = {p0, p1, p2, p3, p4, p5, p6, p7};
        #pragma unroll
        for (int k = 0; k < 8; k++) {
            FFMA2(A[3 * k + 0], x0, av[k]);
            FFMA2(A[3 * k + 1], x1, av[k]);
            FFMA2(A[3 * k + 2], x2, av[k]);
        }
    }

    // ---- epilogue: q + Wc·H + bc ----
    int dglob = chunk * DC + dloc;
    const float* xp = s_xl + dloc * Ff;
    float x00 = xp[0], x01 = xp[1], x02 = xp[2];
    float x10 = xp[3], x11 = xp[4], x12 = xp[5];

    #pragma unroll
    for (int k = 0; k < 8; k++) {
        int c = cg * 8 + k;
        float wc0 = Wc[c * 3 + 0], wc1 = Wc[c * 3 + 1], wc2 = Wc[c * 3 + 2];
        float wq0 = Wq[c * 3 + 0], wq1 = Wq[c * 3 + 1], wq2 = Wq[c * 3 + 2];
        float bcc = bc[c], bqc = bq[c];

        U2F p0, p1, p2;
        p0.u = A[3 * k + 0]; p1.u = A[3 * k + 1]; p2.u = A[3 * k + 2];
        float o0 = fmaf(wc2, p1.f.x, fmaf(wc1, p0.f.y, fmaf(wc0, p0.f.x, bcc)));
        float o1 = fmaf(wc2, p2.f.y, fmaf(wc1, p2.f.x, fmaf(wc0, p1.f.y, bcc)));
        float q0 = fmaf(wq2, x02, fmaf(wq1, x01, fmaf(wq0, x00, bqc)));
        float q1 = fmaf(wq2, x12, fmaf(wq1, x11, fmaf(wq0, x10, bqc)));

        float2 res = make_float2(q0 + o0, q1 + o1);
        *(float2*)(out + (((size_t)b * Cc + c) * Ll + l) * Dd + dglob) = res;
    }
}

extern "C" void kernel_launch(void* const* d_in, const int* in_sizes, int n_in,
                              void* d_out, int out_size)
{
    const float* xl = (const float*)d_in[0];
    const float* xh = (const float*)d_in[1];
    const float* Wq = (const float*)d_in[2];
    const float* bq = (const float*)d_in[3];
    const float* Wm = (const float*)d_in[4];
    const float* bm = (const float*)d_in[5];
    const float* Wc = (const float*)d_in[6];
    const float* bc = (const float*)d_in[7];
    float* out = (float*)d_out;

    static int attr_set = 0;
    if (!attr_set) {
        cudaFuncSetAttribute(k_gram, cudaFuncAttributeMaxDynamicSharedMemorySize,
                             4 * WARP_SMEM * 4);
        cudaFuncSetAttribute(k_out, cudaFuncAttributeMaxDynamicSharedMemorySize,
                             KOUT_SMEM_F * 4);
        attr_set = 1;
    }

    k_gram<<<dim3(18, BL), 128, 4 * WARP_SMEM * 4>>>(xh, xl);
    k_out<<<BL * CHUNKS, 256, KOUT_SMEM_F * 4>>>(
        xl, xh, Wq, bq, Wm, bm, Wc, bc, out);
}

// round 10
// speedup vs baseline: 1.1142x; 1.1142x over previous
#include <cuda_runtime.h>

// MemoryModule: B=8,L=12,T=36,D=1024,F=3,C=32
//   mq[c,t] = sum_{f,g} Wm[c,f] Wq[c,g] G[t,f,g] + bm[c]*(Wq[c]·XLsum)
//           + bq[c]*(Wm[c]·XHsum[t]) + D*bm[c]*bq[c]
//   o[c,d]  = sum_f Wc[c,f] * (sum_t att[c,t]*xh[t,d,f]) + bc[c]
// v10: best-of composition — k_gram v9 (per-warp autonomous pipeline),
//      standalone k_score (XLsum from g_XL), k_out v8 (register-blocked).

#define Bb 8
#define Ll 12
#define Tt 36
#define Dd 1024
#define Ff 3
#define Cc 32
#define BL (Bb * Ll)
#define DF (Dd * Ff)        // 3072
#define DC 128
#define CHUNKS (Dd / DC)    // 8

__device__ __align__(16) float g_G[4 * BL * Tt * 12];  // 4 d-slices of G[9]+XHsum[3]
__device__ __align__(16) float g_XL[4][BL][4];          // per-slice xl sums
__device__ __align__(16) float g_attf[BL * Tt * Cc];    // plain f32 att [bl][t][c]

#define FFMA2(d, a, b) \
    asm("fma.rn.f32x2 %0, %1, %2, %0;" : "+l"(d) : "l"(a), "l"(b))

#define PACKDUP(d, s) \
    asm("mov.b64 %0, {%1, %1};" : "=l"(d) : "f"(s))

#define CP16(dst, src) \
    asm volatile("cp.async.cg.shared.global [%0], [%1], 16;" :: "r"(dst), "l"(src))

union U2F { unsigned long long u; float2 f; };

// ---------------------------------------------------------------------------
// k_gram: CTA = (tg 0..8, dh 0..1, bl), 128 threads, NO CTA barriers.
// Warp w: dseg = w&1, t-pair = tg*4 + (w>>1)*2 + {0,1}. Each warp loads its
// own xl seg + 2 xh segs (own cp.async groups), computes task A while task
// B's loads are in flight. Grid (18,96) x 128.
// ---------------------------------------------------------------------------
#define SEG_F 768                           // floats per 256-d segment
#define WARP_SMEM (3 * SEG_F)               // xl + bufA + bufB

template <bool AXL>
__device__ __forceinline__ void gram_task(
    const float* __restrict__ xp, const float* __restrict__ lp,
    int lane, int bl, int t, int slot)
{
    float V[12];
    #pragma unroll
    for (int j = 0; j < 12; j++) V[j] = 0.0f;
    float X0 = 0.0f, X1 = 0.0f, X2 = 0.0f;

    #pragma unroll
    for (int it = 0; it < 8; it++) {
        int o = it * 96 + lane * 3;
        float a0 = xp[o + 0], a1 = xp[o + 1], a2 = xp[o + 2];
        float b0 = lp[o + 0], b1 = lp[o + 1], b2 = lp[o + 2];
        V[0] = fmaf(a0, b0, V[0]); V[1] = fmaf(a0, b1, V[1]); V[2] = fmaf(a0, b2, V[2]);
        V[3] = fmaf(a1, b0, V[3]); V[4] = fmaf(a1, b1, V[4]); V[5] = fmaf(a1, b2, V[5]);
        V[6] = fmaf(a2, b0, V[6]); V[7] = fmaf(a2, b1, V[7]); V[8] = fmaf(a2, b2, V[8]);
        V[9] += a0; V[10] += a1; V[11] += a2;
        if (AXL) { X0 += b0; X1 += b1; X2 += b2; }
    }

    #pragma unroll
    for (int j = 0; j < 12; j++) {
        #pragma unroll
        for (int o = 16; o; o >>= 1) V[j] += __shfl_down_sync(~0u, V[j], o);
    }
    if (AXL) {
        #pragma unroll
        for (int o = 16; o; o >>= 1) {
            X0 += __shfl_down_sync(~0u, X0, o);
            X1 += __shfl_down_sync(~0u, X1, o);
            X2 += __shfl_down_sync(~0u, X2, o);
        }
    }
    if (lane == 0) {
        float* gp = g_G + (((size_t)slot * BL + bl) * Tt + t) * 12;
        *(float4*)(gp + 0) = make_float4(V[0], V[1], V[2], V[3]);
        *(float4*)(gp + 4) = make_float4(V[4], V[5], V[6], V[7]);
        *(float4*)(gp + 8) = make_float4(V[8], V[9], V[10], V[11]);
        if (AXL) {
            g_XL[slot][bl][0] = X0;
            g_XL[slot][bl][1] = X1;
            g_XL[slot][bl][2] = X2;
        }
    }
}

__global__ __launch_bounds__(128) void k_gram(
    const float* __restrict__ xh_g, const float* __restrict__ xl_g)
{
    extern __shared__ float sg[];           // [4 warps][2304]

    int bx = blockIdx.x, bl = blockIdx.y;
    int tg = bx % 9, dh = bx / 9;
    int tid = threadIdx.x, w = tid >> 5, lane = tid & 31;

    int seg = w & 1;
    int t0 = tg * 4 + (w >> 1) * 2;         // tasks t0, t0+1
    int slot = dh * 2 + seg;

    float* ws   = sg + w * WARP_SMEM;
    float* s_xl = ws;
    float* bA   = ws + SEG_F;
    float* bB   = ws + 2 * SEG_F;

    size_t dof = (size_t)dh * 1536 + seg * SEG_F;
    const float* xls = xl_g + (size_t)bl * DF + dof;
    const float* xh0 = xh_g + ((size_t)bl * Tt + t0) * DF + dof;
    const float* xh1 = xh0 + DF;            // t0+1

    // group 0: xl + task A;  group 1: task B   (all per-thread)
    #pragma unroll
    for (int k = 0; k < 6; k++) {
        int o = (lane + 32 * k) * 4;
        CP16((unsigned)__cvta_generic_to_shared(s_xl + o), xls + o);
        CP16((unsigned)__cvta_generic_to_shared(bA + o), xh0 + o);
    }
    asm volatile("cp.async.commit_group;");
    #pragma unroll
    for (int k = 0; k < 6; k++) {
        int o = (lane + 32 * k) * 4;
        CP16((unsigned)__cvta_generic_to_shared(bB + o), xh1 + o);
    }
    asm volatile("cp.async.commit_group;");

    asm volatile("cp.async.wait_group 1;");
    __syncwarp();
    if (tg == 0 && w < 2)
        gram_task<true>(bA, s_xl, lane, bl, t0, slot);
    else
        gram_task<false>(bA, s_xl, lane, bl, t0, slot);

    asm volatile("cp.async.wait_group 0;");
    __syncwarp();
    gram_task<false>(bB, s_xl, lane, bl, t0 + 1, slot);
}

// ---------------------------------------------------------------------------
// k_score: per bl: sum 4 G slices + XLsum (from g_XL) + scores + softmax
// -> g_attf. Grid 96 x 256.
// ---------------------------------------------------------------------------
__global__ __launch_bounds__(256) void k_score(
    const float* __restrict__ Wq, const float* __restrict__ bq,
    const float* __restrict__ Wm, const float* __restrict__ bm)
{
    __shared__ float s_G[Tt][12];
    __shared__ float s_mq[Cc][Tt];
    __shared__ float s_XL[3];

    int bl = blockIdx.x;
    int tid = threadIdx.x, w = tid >> 5, lane = tid & 31;

    if (tid < 3)
        s_XL[tid] = g_XL[0][bl][tid] + g_XL[1][bl][tid]
                  + g_XL[2][bl][tid] + g_XL[3][bl][tid];
    for (int i = tid; i < Tt * 12; i += 256)
        ((float*)s_G)[i] = g_G[((size_t)0 * BL + bl) * Tt * 12 + i]
                         + g_G[((size_t)1 * BL + bl) * Tt * 12 + i]
                         + g_G[((size_t)2 * BL + bl) * Tt * 12 + i]
                         + g_G[((size_t)3 * BL + bl) * Tt * 12 + i];
    __syncthreads();

    for (int i = tid; i < Cc * Tt; i += 256) {
        int c = i / Tt, t = i - c * Tt;
        float wm0 = Wm[c * 3 + 0], wm1 = Wm[c * 3 + 1], wm2 = Wm[c * 3 + 2];
        float wq0 = Wq[c * 3 + 0], wq1 = Wq[c * 3 + 1], wq2 = Wq[c * 3 + 2];
        float bmc = bm[c], bqc = bq[c];
        const float* Gp = s_G[t];
        float v = wm0 * (wq0 * Gp[0] + wq1 * Gp[1] + wq2 * Gp[2])
                + wm1 * (wq0 * Gp[3] + wq1 * Gp[4] + wq2 * Gp[5])
                + wm2 * (wq0 * Gp[6] + wq1 * Gp[7] + wq2 * Gp[8])
                + bmc * (wq0 * s_XL[0] + wq1 * s_XL[1] + wq2 * s_XL[2])
                + bqc * (wm0 * Gp[9] + wm1 * Gp[10] + wm2 * Gp[11])
                + (float)Dd * bmc * bqc;
        s_mq[c][t] = fmaxf(v, 0.0f);
    }
    __syncthreads();

    #pragma unroll
    for (int k = 0; k < 4; k++) {
        int c = w + 8 * k;
        float v0 = s_mq[c][lane];
        float v1 = (lane < Tt - 32) ? s_mq[c][lane + 32] : -3.0e38f;
        float mx = fmaxf(v0, v1);
        #pragma unroll
        for (int o = 16; o; o >>= 1) mx = fmaxf(mx, __shfl_xor_sync(~0u, mx, o));
        float e0 = __expf(v0 - mx);
        float e1 = (lane < Tt - 32) ? __expf(v1 - mx) : 0.0f;
        float s = e0 + e1;
        #pragma unroll
        for (int o = 16; o; o >>= 1) s += __shfl_xor_sync(~0u, s, o);
        float inv = 1.0f / s;
        float* ap = g_attf + (size_t)bl * Tt * Cc;
        ap[lane * Cc + c] = e0 * inv;
        if (lane < Tt - 32) ap[(lane + 32) * Cc + c] = e1 * inv;
    }
}

// ---------------------------------------------------------------------------
// k_out: CTA = (bl, 128-d chunk). Lane = (cg = lane>>3, dp = lane&7):
// 8 channels x 1 d-pair, 24 FFMA2 accumulators. Structured copy loops,
// explicit mov.b64 packing. Grid 768 x 256, smem ~61KB, 3 CTAs/SM.
// ---------------------------------------------------------------------------
#define SM_TILE_F (Tt * DC * Ff)   // 13824
#define SM_ATT_F  (Tt * Cc)        // 1152 floats = 288 cp16
#define SM_XL_F   (DC * Ff)        // 384 floats = 96 cp16
#define T_SPLIT   12

__global__ __launch_bounds__(256, 3) void k_out(
    const float* __restrict__ xl_g, const float* __restrict__ xh_g,
    const float* __restrict__ Wq, const float* __restrict__ bq,
    const float* __restrict__ Wc, const float* __restrict__ bc,
    float* __restrict__ out)
{
    extern __shared__ float sm[];
    float* s_tile = sm;
    float* s_att  = sm + SM_TILE_F;
    float* s_xl   = sm + SM_TILE_F + SM_ATT_F;

    int blk = blockIdx.x;
    int bl = blk / CHUNKS, chunk = blk - bl * CHUNKS;
    int b = bl / Ll, l = bl - b * Ll;
    int tid = threadIdx.x;
    int wid = tid >> 5, lane = tid & 31;

    const float* xh_bl   = xh_g + (size_t)bl * Tt * DF + chunk * DC * Ff;
    const float* att_src = g_attf + (size_t)bl * Tt * Cc;
    const float* xl_src  = xl_g + (size_t)bl * DF + chunk * DC * Ff;

    // ---- stage A: att (288 cp16) + xl (96 cp16) + tile rows [0,12) ----
    {
        CP16((unsigned)__cvta_generic_to_shared(s_att + tid * 4), att_src + tid * 4);
        int i2 = tid + 256;
        if (i2 < 288)
            CP16((unsigned)__cvta_generic_to_shared(s_att + i2 * 4), att_src + i2 * 4);
        int j = tid - 160;
        if (j >= 0)
            CP16((unsigned)__cvta_generic_to_shared(s_xl + j * 4), xl_src + j * 4);
    }
    #pragma unroll
    for (int rr = 0; rr < 2; rr++) {
        int r = wid + rr * 8;
        if (r < T_SPLIT) {
            const float* sb = xh_bl + (size_t)r * DF;
            float* db = s_tile + r * (DC * Ff);
            #pragma unroll
            for (int s = 0; s < 3; s++) {
                int off = s * 128 + lane * 4;
                CP16((unsigned)__cvta_generic_to_shared(db + off), sb + off);
            }
        }
    }
    asm volatile("cp.async.commit_group;");

    // ---- stage B: tile rows [12,36) ----
    #pragma unroll
    for (int rr = 0; rr < 3; rr++) {
        int r = T_SPLIT + wid + rr * 8;
        const float* sb = xh_bl + (size_t)r * DF;
        float* db = s_tile + r * (DC * Ff);
        #pragma unroll
        for (int s = 0; s < 3; s++) {
            int off = s * 128 + lane * 4;
            CP16((unsigned)__cvta_generic_to_shared(db + off), sb + off);
        }
    }
    asm volatile("cp.async.commit_group;");

    int cg = lane >> 3, dp = lane & 7;
    int dloc = wid * 16 + dp * 2;

    unsigned long long A[24];
    #pragma unroll
    for (int k = 0; k < 24; k++) A[k] = 0ull;

    const float* ab = s_att + cg * 8;                    // + t*32
    const unsigned long long* tb =
        (const unsigned long long*)(s_tile + dloc * Ff); // + t*192 (u64 units)

    asm volatile("cp.async.wait_group 1;");
    __syncthreads();

    #pragma unroll 2
    for (int t = 0; t < T_SPLIT; t++) {
        float4 a0 = *(const float4*)(ab + t * Cc);
        float4 a1 = *(const float4*)(ab + t * Cc + 4);
        unsigned long long x0 = tb[t * 192 + 0];
        unsigned long long x1 = tb[t * 192 + 1];
        unsigned long long x2 = tb[t * 192 + 2];
        unsigned long long p0, p1, p2, p3, p4, p5, p6, p7;
        PACKDUP(p0, a0.x); PACKDUP(p1, a0.y); PACKDUP(p2, a0.z); PACKDUP(p3, a0.w);
        PACKDUP(p4, a1.x); PACKDUP(p5, a1.y); PACKDUP(p6, a1.z); PACKDUP(p7, a1.w);
        unsigned long long av[8] = {p0, p1, p2, p3, p4, p5, p6, p7};
        #pragma unroll
        for (int k = 0; k < 8; k++) {
            FFMA2(A[3 * k + 0], x0, av[k]);
            FFMA2(A[3 * k + 1], x1, av[k]);
            FFMA2(A[3 * k + 2], x2, av[k]);
        }
    }

    asm volatile("cp.async.wait_group 0;");
    __syncthreads();

    #pragma unroll 2
    for (int t = T_SPLIT; t < Tt; t++) {
        float4 a0 = *(const float4*)(ab + t * Cc);
        float4 a1 = *(const float4*)(ab + t * Cc + 4);
        unsigned long long x0 = tb[t * 192 + 0];
        unsigned long long x1 = tb[t * 192 + 1];
        unsigned long long x2 = tb[t * 192 + 2];
        unsigned long long p0, p1, p2, p3, p4, p5, p6, p7;
        PACKDUP(p0, a0.x); PACKDUP(p1, a0.y); PACKDUP(p2, a0.z); PACKDUP(p3, a0.w);
        PACKDUP(p4, a1.x); PACKDUP(p5, a1.y); PACKDUP(p6, a1.z); PACKDUP(p7, a1.w);
        unsigned long long av[8] = {p0, p1, p2, p3, p4, p5, p6, p7};
        #pragma unroll
        for (int k = 0; k < 8; k++) {
            FFMA2(A[3 * k + 0], x0, av[k]);
            FFMA2(A[3 * k + 1], x1, av[k]);
            FFMA2(A[3 * k + 2], x2, av[k]);
        }
    }

    // ---- epilogue: q + Wc·H + bc ----
    int dglob = chunk * DC + dloc;
    const float* xp = s_xl + dloc * Ff;
    float x00 = xp[0], x01 = xp[1], x02 = xp[2];
    float x10 = xp[3], x11 = xp[4], x12 = xp[5];

    #pragma unroll
    for (int k = 0; k < 8; k++) {
        int c = cg * 8 + k;
        float wc0 = Wc[c * 3 + 0], wc1 = Wc[c * 3 + 1], wc2 = Wc[c * 3 + 2];
        float wq0 = Wq[c * 3 + 0], wq1 = Wq[c * 3 + 1], wq2 = Wq[c * 3 + 2];
        float bcc = bc[c], bqc = bq[c];

        U2F p0, p1, p2;
        p0.u = A[3 * k + 0]; p1.u = A[3 * k + 1]; p2.u = A[3 * k + 2];
        float o0 = fmaf(wc2, p1.f.x, fmaf(wc1, p0.f.y, fmaf(wc0, p0.f.x, bcc)));
        float o1 = fmaf(wc2, p2.f.y, fmaf(wc1, p2.f.x, fmaf(wc0, p1.f.y, bcc)));
        float q0 = fmaf(wq2, x02, fmaf(wq1, x01, fmaf(wq0, x00, bqc)));
        float q1 = fmaf(wq2, x12, fmaf(wq1, x11, fmaf(wq0, x10, bqc)));

        float2 res = make_float2(q0 + o0, q1 + o1);
        *(float2*)(out + (((size_t)b * Cc + c) * Ll + l) * Dd + dglob) = res;
    }
}

extern "C" void kernel_launch(void* const* d_in, const int* in_sizes, int n_in,
                              void* d_out, int out_size)
{
    const float* xl = (const float*)d_in[0];
    const float* xh = (const float*)d_in[1];
    const float* Wq = (const float*)d_in[2];
    const float* bq = (const float*)d_in[3];
    const float* Wm = (const float*)d_in[4];
    const float* bm = (const float*)d_in[5];
    const float* Wc = (const float*)d_in[6];
    const float* bc = (const float*)d_in[7];
    float* out = (float*)d_out;

    static int attr_set = 0;
    if (!attr_set) {
        cudaFuncSetAttribute(k_gram, cudaFuncAttributeMaxDynamicSharedMemorySize,
                             4 * WARP_SMEM * 4);
        cudaFuncSetAttribute(k_out, cudaFuncAttributeMaxDynamicSharedMemorySize,
                             (SM_TILE_F + SM_ATT_F + SM_XL_F) * 4);
        attr_set = 1;
    }

    k_gram<<<dim3(18, BL), 128, 4 * WARP_SMEM * 4>>>(xh, xl);
    k_score<<<BL, 256>>>(Wq, bq, Wm, bm);
    k_out<<<BL * CHUNKS, 256, (SM_TILE_F + SM_ATT_F + SM_XL_F) * 4>>>(
        xl, xh, Wq, bq, Wc, bc, out);
}